// round 7
// baseline (speedup 1.0000x reference)
#include <cuda_runtime.h>
#include <cuda_fp16.h>
#include <cooperative_groups.h>
#include <cstdint>

namespace cg = cooperative_groups;

#define D 64
#define NODE_STRIDE 256        // 4 layers * 64 floats, node-major [n][4][64]
#define MAX_NODES   150016
#define MAX_EDGES   3000000
#define TPB         256
#define SEG         512        // scan segment size (2 elems per thread)

// ---------------------------------------------------------------------------
// Static scratch (allocation-free rule: __device__ globals)
// ---------------------------------------------------------------------------
__device__ int     d_cnt[MAX_NODES];
__device__ int     d_row_ptr[MAX_NODES + 1];
__device__ int     d_cursor[MAX_NODES];
__device__ int     d_bsums[2048];
__device__ int2    d_edges_sorted[MAX_EDGES];       // (col, val bits), grouped by row
__device__ __half2 d_shadow[2][MAX_NODES * 32];     // fp16 ping-pong embeddings, 128B/row

// ---------------------------------------------------------------------------
// SpMM pass (EXACT round-6 inner loop), warp grid-stride over rows.
// ---------------------------------------------------------------------------
__device__ __forceinline__ void spmm_pass(
        const __half2* __restrict__ xh,       // shadow in
        __half2*       __restrict__ xh_out,   // shadow out (may be null)
        float*         __restrict__ y_base,   // embs + l*64
        int n, int gwarp, int nwarp, int lane,
        float* __restrict__ users, float* __restrict__ items,
        int n_users, int do_mean) {
    for (int row = gwarp; row < n; row += nwarp) {
        int start = d_row_ptr[row];
        int end   = d_row_ptr[row + 1];

        float ax = 0.f, ay = 0.f, bx = 0.f, by = 0.f;

        int e = start;
        for (; e + 1 < end; e += 2) {
            int2 m0 = d_edges_sorted[e];
            int2 m1 = d_edges_sorted[e + 1];
            float w0 = __int_as_float(m0.y);
            float w1 = __int_as_float(m1.y);
            float2 v0 = __half22float2(xh[(size_t)m0.x * 32 + lane]);
            float2 v1 = __half22float2(xh[(size_t)m1.x * 32 + lane]);
            ax += w0 * v0.x;  ay += w0 * v0.y;
            bx += w1 * v1.x;  by += w1 * v1.y;
        }
        if (e < end) {
            int2 m0 = d_edges_sorted[e];
            float w0 = __int_as_float(m0.y);
            float2 v0 = __half22float2(xh[(size_t)m0.x * 32 + lane]);
            ax += w0 * v0.x;  ay += w0 * v0.y;
        }

        float rx = ax + bx;
        float ry = ay + by;

        reinterpret_cast<float2*>(y_base + (size_t)row * NODE_STRIDE)[lane] =
            make_float2(rx, ry);

        if (xh_out)
            xh_out[(size_t)row * 32 + lane] = __float22half2_rn(make_float2(rx, ry));

        if (do_mean) {
            const float* nb = y_base - 3 * D + (size_t)row * NODE_STRIDE;
            float2 l0 = reinterpret_cast<const float2*>(nb)[lane];
            float2 l1 = reinterpret_cast<const float2*>(nb + D)[lane];
            float2 l2 = reinterpret_cast<const float2*>(nb + 2 * D)[lane];
            float mx = (l0.x + l1.x + l2.x + rx) * 0.25f;
            float my = (l0.y + l1.y + l2.y + ry) * 0.25f;
            float* dst = (row < n_users)
                ? users + (size_t)row * D
                : items + (size_t)(row - n_users) * D;
            reinterpret_cast<float2*>(dst)[lane] = make_float2(mx, my);
        }
    }
}

// ---------------------------------------------------------------------------
// One cooperative kernel: init + CSR build + 3 SpMM layers + fused mean.
// ---------------------------------------------------------------------------
__global__ void __launch_bounds__(TPB)
lgcn_fused(const float* __restrict__ user_emb,
           const float* __restrict__ item_emb,
           const int*   __restrict__ edge_row,
           const int*   __restrict__ edge_col,
           const float* __restrict__ edge_val,
           float* __restrict__ embs,
           float* __restrict__ users,
           float* __restrict__ items,
           int n_users, int n, int n_edges) {
    cg::grid_group grid = cg::this_grid();
    const int t    = threadIdx.x;
    const int tid  = blockIdx.x * TPB + t;
    const int nthr = gridDim.x * TPB;
    const int lane = t & 31;
    const int gwarp = tid >> 5;
    const int nwarp = nthr >> 5;

    __shared__ int s[TPB];

    // ---- Phase 0: zero cnt; init embs layer0 + fp16 shadow0 ----
    for (int i = tid; i < n; i += nthr) d_cnt[i] = 0;
    {
        int total = n * 16;
        for (int idx = tid; idx < total; idx += nthr) {
            int node = idx >> 4;
            int q    = idx & 15;
            const float4* src = (node < n_users)
                ? reinterpret_cast<const float4*>(user_emb + (size_t)node * D)
                : reinterpret_cast<const float4*>(item_emb + (size_t)(node - n_users) * D);
            float4 v = src[q];
            reinterpret_cast<float4*>(embs + (size_t)node * NODE_STRIDE)[q] = v;
            d_shadow[0][(size_t)node * 32 + q * 2]     = __float22half2_rn(make_float2(v.x, v.y));
            d_shadow[0][(size_t)node * 32 + q * 2 + 1] = __float22half2_rn(make_float2(v.z, v.w));
        }
    }
    grid.sync();

    // ---- Phase 1: histogram ----
    for (int e = tid; e < n_edges; e += nthr)
        atomicAdd(&d_cnt[edge_row[e]], 1);
    grid.sync();

    // ---- Phase 2: segmented exclusive scan (SEG=512 per segment) ----
    int nseg = (n + SEG - 1) / SEG;
    for (int seg = blockIdx.x; seg < nseg; seg += gridDim.x) {
        int base = seg * SEG;
        int i0 = base + 2 * t;
        int i1 = i0 + 1;
        int a = (i0 < n) ? d_cnt[i0] : 0;
        int b = (i1 < n) ? d_cnt[i1] : 0;
        int tot = a + b;
        s[t] = tot;
        __syncthreads();
        #pragma unroll
        for (int off = 1; off < TPB; off <<= 1) {
            int x = (t >= off) ? s[t - off] : 0;
            __syncthreads();
            s[t] += x;
            __syncthreads();
        }
        int excl = s[t] - tot;                 // exclusive prefix of this pair
        if (i0 < n) d_row_ptr[i0] = excl;
        if (i1 < n) d_row_ptr[i1] = excl + a;
        if (t == TPB - 1) d_bsums[seg] = s[TPB - 1];
        __syncthreads();
    }
    grid.sync();

    // ---- Phase 3: block 0 scans segment sums (exclusive) ----
    if (blockIdx.x == 0) {
        int chunk = (nseg + TPB - 1) / TPB;    // <= 8 for n <= 150016
        int lv[8];
        int b0 = t * chunk;
        int lsum = 0;
        for (int j = 0; j < chunk; ++j) {
            int i = b0 + j;
            lv[j] = (i < nseg) ? d_bsums[i] : 0;
            lsum += lv[j];
        }
        s[t] = lsum;
        __syncthreads();
        #pragma unroll
        for (int off = 1; off < TPB; off <<= 1) {
            int x = (t >= off) ? s[t - off] : 0;
            __syncthreads();
            s[t] += x;
            __syncthreads();
        }
        int excl = s[t] - lsum;
        for (int j = 0; j < chunk; ++j) {
            int i = b0 + j;
            if (i < nseg) { d_bsums[i] = excl; excl += lv[j]; }
        }
    }
    grid.sync();

    // ---- Phase 4: add segment offsets; init cursor ----
    for (int i = tid; i < n; i += nthr) {
        int p = d_row_ptr[i] + d_bsums[i / SEG];
        d_row_ptr[i] = p;
        d_cursor[i]  = p;
    }
    if (tid == 0) d_row_ptr[n] = n_edges;
    grid.sync();

    // ---- Phase 5: scatter edges into CSR order ----
    for (int e = tid; e < n_edges; e += nthr) {
        int r = edge_row[e];
        int p = atomicAdd(&d_cursor[r], 1);
        d_edges_sorted[p] = make_int2(edge_col[e], __float_as_int(edge_val[e]));
    }
    grid.sync();

    // ---- Phases 6-8: three SpMM layers (fp16 shadow ping-pong) ----
    __half2* sh0 = &d_shadow[0][0];
    __half2* sh1 = &d_shadow[1][0];

    spmm_pass(sh0, sh1, embs + 1 * D, n, gwarp, nwarp, lane,
              users, items, n_users, 0);
    grid.sync();
    spmm_pass(sh1, sh0, embs + 2 * D, n, gwarp, nwarp, lane,
              users, items, n_users, 0);
    grid.sync();
    spmm_pass(sh0, nullptr, embs + 3 * D, n, gwarp, nwarp, lane,
              users, items, n_users, 1);
}

// ---------------------------------------------------------------------------
// out layout = [users (n_users*64)] [items (n_items*64)] [embs (n*4*64)]
// ---------------------------------------------------------------------------
extern "C" void kernel_launch(void* const* d_in, const int* in_sizes, int n_in,
                              void* d_out, int out_size) {
    const float* user_emb = (const float*)d_in[0];
    const float* item_emb = (const float*)d_in[1];
    const int*   edge_row = (const int*)d_in[2];
    const int*   edge_col = (const int*)d_in[3];
    const float* edge_val = (const float*)d_in[4];

    int n_users = in_sizes[0] / D;
    int n_items = in_sizes[1] / D;
    int n       = n_users + n_items;
    int n_edges = in_sizes[2];

    float* out   = (float*)d_out;
    float* users = out;
    float* items = out + (size_t)n_users * D;
    float* embs  = out + (size_t)n * D;   // [n][4][64]

    // Cooperative grid: all blocks co-resident.
    int dev = 0;
    cudaGetDevice(&dev);
    int sms = 0;
    cudaDeviceGetAttribute(&sms, cudaDevAttrMultiProcessorCount, dev);
    int perSM = 0;
    cudaOccupancyMaxActiveBlocksPerMultiprocessor(&perSM, (const void*)lgcn_fused,
                                                  TPB, 0);
    if (perSM < 1) perSM = 1;
    int blocks = sms * perSM;

    void* args[] = {
        (void*)&user_emb, (void*)&item_emb,
        (void*)&edge_row, (void*)&edge_col, (void*)&edge_val,
        (void*)&embs, (void*)&users, (void*)&items,
        (void*)&n_users, (void*)&n, (void*)&n_edges
    };
    cudaLaunchCooperativeKernel((const void*)lgcn_fused,
                                dim3(blocks), dim3(TPB), args, 0, 0);
}

// round 8
// speedup vs baseline: 1.9438x; 1.9438x over previous
#include <cuda_runtime.h>
#include <cuda_fp16.h>
#include <cstdint>

#define D 64
#define NODE_STRIDE 256        // 4 layers * 64 floats, node-major [n][4][64]
#define MAX_NODES   150016
#define MAX_EDGES   3000000
#define SCAN_BS     512
#define MAX_SEGS    ((MAX_NODES + SCAN_BS - 1) / SCAN_BS)   // 293

// ---------------------------------------------------------------------------
// Static scratch (allocation-free rule: __device__ globals)
// ---------------------------------------------------------------------------
__device__ int     d_cnt[MAX_NODES];
__device__ int     d_row_ptr[MAX_NODES + 1];
__device__ int     d_cursor[MAX_NODES];
__device__ int     d_bsums[SCAN_BS];
__device__ int2    d_edges_sorted[MAX_EDGES];        // (col, val bits), grouped by row
__device__ __half2 d_shadow[2][MAX_NODES * 32];      // fp16 ping-pong embeddings, 128B/row

// ---------------------------------------------------------------------------
// Fused: embs layer0 + fp16 shadow0 init  AND  row histogram.
// Thread range [0, n*16)          -> init work
// Thread range [n*16, n*16+edges) -> hist work
// ---------------------------------------------------------------------------
__global__ void lgcn_init_hist(const float* __restrict__ user_emb,
                               const float* __restrict__ item_emb,
                               const int*   __restrict__ edge_row,
                               float* __restrict__ embs,
                               int n_users, int n, int n_edges) {
    int idx = blockIdx.x * blockDim.x + threadIdx.x;
    int init_total = n * 16;
    if (idx < init_total) {
        int node = idx >> 4;
        int q    = idx & 15;
        const float4* src = (node < n_users)
            ? reinterpret_cast<const float4*>(user_emb + (size_t)node * D)
            : reinterpret_cast<const float4*>(item_emb + (size_t)(node - n_users) * D);
        float4 v = src[q];
        reinterpret_cast<float4*>(embs + (size_t)node * NODE_STRIDE)[q] = v;
        d_shadow[0][(size_t)node * 32 + q * 2]     = __float22half2_rn(make_float2(v.x, v.y));
        d_shadow[0][(size_t)node * 32 + q * 2 + 1] = __float22half2_rn(make_float2(v.z, v.w));
    } else {
        int e = idx - init_total;
        if (e < n_edges) atomicAdd(&d_cnt[edge_row[e]], 1);
    }
}

// ---------------------------------------------------------------------------
// Segmented exclusive scan of d_cnt -> d_row_ptr (partial); totals -> d_bsums
// ---------------------------------------------------------------------------
__global__ void lgcn_scan_blocks(int n) {
    __shared__ int s[SCAN_BS];
    int t = threadIdx.x;
    int i = blockIdx.x * SCAN_BS + t;
    int v = (i < n) ? d_cnt[i] : 0;
    s[t] = v;
    __syncthreads();
    #pragma unroll
    for (int off = 1; off < SCAN_BS; off <<= 1) {
        int tmp = (t >= off) ? s[t - off] : 0;
        __syncthreads();
        s[t] += tmp;
        __syncthreads();
    }
    if (i < n) d_row_ptr[i] = s[t] - v;      // exclusive within segment
    if (t == SCAN_BS - 1) d_bsums[blockIdx.x] = s[t];
}

// ---------------------------------------------------------------------------
// Fused: every block redundantly scans the <=293 segment sums in smem, then
// applies its segment's offset and initializes the cursor. Removes the
// single-block scan_sums kernel.
// ---------------------------------------------------------------------------
__global__ void lgcn_scan_finish(int n, int nseg, int n_edges) {
    __shared__ int s[SCAN_BS];
    int t = threadIdx.x;
    int v = (t < nseg) ? d_bsums[t] : 0;
    s[t] = v;
    __syncthreads();
    #pragma unroll
    for (int off = 1; off < SCAN_BS; off <<= 1) {
        int tmp = (t >= off) ? s[t - off] : 0;
        __syncthreads();
        s[t] += tmp;
        __syncthreads();
    }
    // s[k] is now inclusive prefix; exclusive offset of segment k = s[k] - bsums[k]
    __syncthreads();

    int i = blockIdx.x * SCAN_BS + t;
    if (i < n) {
        int seg = i / SCAN_BS;   // == blockIdx.x (SCAN_BS threads per block)
        int segv = d_bsums[seg];
        int off  = s[seg] - segv;
        int p = d_row_ptr[i] + off;
        d_row_ptr[i] = p;
        d_cursor[i]  = p;
    }
    if (i == 0) d_row_ptr[n] = n_edges;
}

__global__ void lgcn_scatter(const int*   __restrict__ edge_row,
                             const int*   __restrict__ edge_col,
                             const float* __restrict__ edge_val,
                             int n_edges) {
    int e = blockIdx.x * blockDim.x + threadIdx.x;
    if (e >= n_edges) return;
    int r = edge_row[e];
    int p = atomicAdd(&d_cursor[r], 1);
    d_edges_sorted[p] = make_int2(edge_col[e], __float_as_int(edge_val[e]));
}

// ---------------------------------------------------------------------------
// SpMM, CSR, warp-per-row — EXACT round-6 winner. fp16 gather, fp32 accum,
// fp32 layer write + fp16 shadow write; layer 3 fuses the 4-layer mean.
// ---------------------------------------------------------------------------
__global__ void lgcn_spmm_csr(const __half2* __restrict__ xh,      // shadow in
                              __half2*       __restrict__ xh_out,  // shadow out (may be null)
                              float*         __restrict__ y_base,  // embs + l*64
                              int n,
                              float* __restrict__ users,
                              float* __restrict__ items,
                              int n_users, int do_mean) {
    int warp = (blockIdx.x * blockDim.x + threadIdx.x) >> 5;
    int lane = threadIdx.x & 31;
    if (warp >= n) return;

    int start = d_row_ptr[warp];
    int end   = d_row_ptr[warp + 1];

    float ax = 0.f, ay = 0.f, bx = 0.f, by = 0.f;

    int e = start;
    for (; e + 1 < end; e += 2) {
        int2 m0 = d_edges_sorted[e];
        int2 m1 = d_edges_sorted[e + 1];
        float w0 = __int_as_float(m0.y);
        float w1 = __int_as_float(m1.y);
        float2 v0 = __half22float2(xh[(size_t)m0.x * 32 + lane]);
        float2 v1 = __half22float2(xh[(size_t)m1.x * 32 + lane]);
        ax += w0 * v0.x;  ay += w0 * v0.y;
        bx += w1 * v1.x;  by += w1 * v1.y;
    }
    if (e < end) {
        int2 m0 = d_edges_sorted[e];
        float w0 = __int_as_float(m0.y);
        float2 v0 = __half22float2(xh[(size_t)m0.x * 32 + lane]);
        ax += w0 * v0.x;  ay += w0 * v0.y;
    }

    float rx = ax + bx;
    float ry = ay + by;

    reinterpret_cast<float2*>(y_base + (size_t)warp * NODE_STRIDE)[lane] =
        make_float2(rx, ry);

    if (xh_out)
        xh_out[(size_t)warp * 32 + lane] = __float22half2_rn(make_float2(rx, ry));

    if (do_mean) {
        // y_base == embs + 3*D here; node block base = y_base - 3*D
        const float* nb = y_base - 3 * D + (size_t)warp * NODE_STRIDE;
        float2 l0 = reinterpret_cast<const float2*>(nb)[lane];
        float2 l1 = reinterpret_cast<const float2*>(nb + D)[lane];
        float2 l2 = reinterpret_cast<const float2*>(nb + 2 * D)[lane];
        float mx = (l0.x + l1.x + l2.x + rx) * 0.25f;
        float my = (l0.y + l1.y + l2.y + ry) * 0.25f;
        float* dst = (warp < n_users)
            ? users + (size_t)warp * D
            : items + (size_t)(warp - n_users) * D;
        reinterpret_cast<float2*>(dst)[lane] = make_float2(mx, my);
    }
}

// ---------------------------------------------------------------------------
// out layout = [users (n_users*64)] [items (n_items*64)] [embs (n*4*64)]
// ---------------------------------------------------------------------------
extern "C" void kernel_launch(void* const* d_in, const int* in_sizes, int n_in,
                              void* d_out, int out_size) {
    const float* user_emb = (const float*)d_in[0];
    const float* item_emb = (const float*)d_in[1];
    const int*   edge_row = (const int*)d_in[2];
    const int*   edge_col = (const int*)d_in[3];
    const float* edge_val = (const float*)d_in[4];

    int n_users = in_sizes[0] / D;
    int n_items = in_sizes[1] / D;
    int n       = n_users + n_items;
    int n_edges = in_sizes[2];

    float* out   = (float*)d_out;
    float* users = out;
    float* items = out + (size_t)n_users * D;
    float* embs  = out + (size_t)n * D;   // [n][4][64]

    const int TPB = 256;
    int nseg = (n + SCAN_BS - 1) / SCAN_BS;

    // --- zero counts (graph memset node) ---
    {
        void* cnt_ptr = nullptr;
        cudaGetSymbolAddress(&cnt_ptr, d_cnt);
        cudaMemsetAsync(cnt_ptr, 0, (size_t)n * sizeof(int), 0);
    }

    // --- fused init + hist ---
    {
        int total = n * 16 + n_edges;
        lgcn_init_hist<<<(total + TPB - 1) / TPB, TPB>>>(user_emb, item_emb, edge_row,
                                                         embs, n_users, n, n_edges);
    }

    // --- scan (2 kernels) ---
    lgcn_scan_blocks<<<nseg, SCAN_BS>>>(n);
    lgcn_scan_finish<<<nseg, SCAN_BS>>>(n, nseg, n_edges);

    // --- scatter edges into CSR order ---
    lgcn_scatter<<<(n_edges + TPB - 1) / TPB, TPB>>>(edge_row, edge_col, edge_val, n_edges);

    // --- 3 SpMM layers; fp16 shadow ping-pong; layer 3 fuses the mean ---
    {
        __half2* sh0 = nullptr;
        __half2* sh1 = nullptr;
        cudaGetSymbolAddress((void**)&sh0, d_shadow);
        sh1 = sh0 + (size_t)MAX_NODES * 32;

        long long threads = (long long)n * 32;
        int grid = (int)((threads + TPB - 1) / TPB);

        lgcn_spmm_csr<<<grid, TPB>>>(sh0, sh1, embs + 1 * D, n,
                                     users, items, n_users, 0);
        lgcn_spmm_csr<<<grid, TPB>>>(sh1, sh0, embs + 2 * D, n,
                                     users, items, n_users, 0);
        lgcn_spmm_csr<<<grid, TPB>>>(sh0, nullptr, embs + 3 * D, n,
                                     users, items, n_users, 1);
    }
}